// round 2
// baseline (speedup 1.0000x reference)
#include <cuda_runtime.h>
#include <math.h>

// ---------------------------------------------------------------------------
// HierarchicalCNN: two 3-layer strided conv1d nets + pooled heads + routing.
//
//   x    : [512, 2, 4096]
//   a1   : [512, 128, 1024]  (conv1 out, scratch, reused per net)
//   feat : [2][512][256]     (pooled sums; /512 in head)
//   out  : [512, 4]
//
// conv0 (2->64) is fused into conv1 (64->128): each conv1 CTA recomputes the
// 260-wide layer-0 activation window it needs from x directly in smem.
//
// SAME padding, stride 2, K=5: pad_lo = 1 -> input index = 2*t + k - 1.
// ---------------------------------------------------------------------------

__device__ float g_a1[(size_t)512 * 128 * 1024];
__device__ float g_feat[2][512][256];

// ---------------------------------------------------------------------------
// conv01: x[B,2,4096] -> (conv0+relu, recomputed per tile) -> conv1+relu
//         -> a1[B,128,1024]
// CTA: one (sample b, 128-wide t tile); covers all 128 c_out.
// 256 threads, 8x8 register blocking over (c_out=128) x (t=128).
// K-dim = 64 c_mid * 5 taps, streamed in c_mid tiles of 8.
// ---------------------------------------------------------------------------
__global__ __launch_bounds__(256, 2)
void conv01_kernel(const float* __restrict__ x,
                   const float* __restrict__ w0,  // [64,2,5]
                   const float* __restrict__ b0,  // [64]
                   const float* __restrict__ w1,  // [128,64,5]
                   const float* __restrict__ b1,  // [128]
                   float* __restrict__ out)       // [512,128,1024]
{
    const int b    = blockIdx.x;
    const int tt0  = blockIdx.y * 128;   // layer-1 output t tile start
    const int tid  = threadIdx.x;
    const int tx   = tid & 15;           // t groups
    const int ty   = tid >> 4;           // c_out groups

    // layer-0 t (mid) window needed: [2*tt0-1, 2*tt0+258] -> 260 values
    const int tmid0 = 2 * tt0 - 1;
    // x window needed for those: [2*tmid0-1, 2*tmid0+521] -> 523 values
    const int x0 = 2 * tmid0 - 1;

    __shared__ float xs0[2][524];    // raw x window (zero-padded)
    __shared__ float w0s[64 * 10];   // conv0 weights
    __shared__ float b0s[64];
    __shared__ float ws[40][129];    // conv1 W tile [ci*5+k][co], pitch 129
    __shared__ float xs[8][260];     // layer-0 activations [ci][t-halo]

    for (int i = tid; i < 640; i += 256) w0s[i] = w0[i];
    if (tid < 64) b0s[tid] = b0[tid];

    const float* xb = x + (size_t)b * 2 * 4096;
    for (int i = tid; i < 2 * 524; i += 256) {
        int row = i / 524, col = i % 524;
        int gx = x0 + col;
        xs0[row][col] = (gx >= 0 && gx < 4096) ? xb[(size_t)row * 4096 + gx] : 0.0f;
    }

    float acc[8][8];
#pragma unroll
    for (int i = 0; i < 8; i++)
#pragma unroll
        for (int j = 0; j < 8; j++) acc[i][j] = 0.0f;

    __syncthreads();

    for (int ci0 = 0; ci0 < 64; ci0 += 8) {
        // conv1 W tile: 40 x 128 = 5120 elems, 20 per thread.
#pragma unroll
        for (int r = 0; r < 20; r++) {
            int flat = r * 256 + tid;
            int co = flat / 40;
            int kk = flat % 40;
            ws[kk][co] = w1[(size_t)co * (64 * 5) + ci0 * 5 + kk];
        }
        // compute layer-0 activations for this ci tile: 8 x 260 values.
        // a0[ci][t] = relu(b0[ci] + sum_{ic<2,k<5} w0[ci][ic*5+k]*x[ic][2t-1+k])
        // x smem col for (t=tmid0+col, k) = 2*col + k.
        for (int i = tid; i < 8 * 260; i += 256) {
            int row = i / 260, col = i % 260;
            int ci = ci0 + row;
            int tmid = tmid0 + col;
            float v = 0.0f;
            if (tmid >= 0 && tmid < 2048) {
                float a = b0s[ci];
                const float* wc = &w0s[ci * 10];
#pragma unroll
                for (int k = 0; k < 5; k++) a = fmaf(wc[k],     xs0[0][2 * col + k], a);
#pragma unroll
                for (int k = 0; k < 5; k++) a = fmaf(wc[5 + k], xs0[1][2 * col + k], a);
                v = fmaxf(a, 0.0f);
            }
            xs[row][col] = v;
        }
        __syncthreads();

#pragma unroll
        for (int ci = 0; ci < 8; ci++) {
#pragma unroll
            for (int k = 0; k < 5; k++) {
                float a[8], bb[8];
#pragma unroll
                for (int j = 0; j < 8; j++) a[j] = ws[ci * 5 + k][ty + 16 * j];
#pragma unroll
                for (int j = 0; j < 8; j++) bb[j] = xs[ci][2 * (tx + 16 * j) + k];
#pragma unroll
                for (int cj = 0; cj < 8; cj++)
#pragma unroll
                    for (int tj = 0; tj < 8; tj++)
                        acc[cj][tj] = fmaf(a[cj], bb[tj], acc[cj][tj]);
            }
        }
        __syncthreads();
    }

#pragma unroll
    for (int cj = 0; cj < 8; cj++) {
        int co = ty + 16 * cj;
        float bv = b1[co];
        float* ob = out + ((size_t)b * 128 + co) * 1024 + tt0;
#pragma unroll
        for (int tj = 0; tj < 8; tj++) {
            int t = tx + 16 * tj;
            ob[t] = fmaxf(acc[cj][tj] + bv, 0.0f);
        }
    }
}

// ---------------------------------------------------------------------------
// conv2: a1[B,128,1024] -> conv+relu -> fused mean-pool into feat sums.
// CTA tile: 128 c_out x 128 t, 256 threads, 8x8 register blocking.
// ---------------------------------------------------------------------------
__global__ __launch_bounds__(256, 2)
void conv2_kernel(const float* __restrict__ in,    // [B,128,1024]
                  const float* __restrict__ w,     // [256,128,5]
                  const float* __restrict__ bias,  // [256]
                  float* __restrict__ feat)        // [B,256] sums
{
    const int b   = blockIdx.x;
    const int tt0 = blockIdx.y * 128;
    const int co0 = blockIdx.z * 128;
    const int tid = threadIdx.x;
    const int tx = tid & 15;
    const int ty = tid >> 4;

    __shared__ float ws[40][129];
    __shared__ float xs[8][260];

    float acc[8][8];
#pragma unroll
    for (int i = 0; i < 8; i++)
#pragma unroll
        for (int j = 0; j < 8; j++) acc[i][j] = 0.0f;

    const float* inb = in + (size_t)b * 128 * 1024;

    for (int ci0 = 0; ci0 < 128; ci0 += 8) {
#pragma unroll
        for (int r = 0; r < 20; r++) {
            int flat = r * 256 + tid;
            int co = flat / 40;
            int kk = flat % 40;
            ws[kk][co] = w[(size_t)(co0 + co) * (128 * 5) + ci0 * 5 + kk];
        }
        for (int i = tid; i < 8 * 260; i += 256) {
            int row = i / 260, col = i % 260;
            int gt = 2 * tt0 - 1 + col;
            xs[row][col] = (gt >= 0 && gt < 1024)
                               ? inb[(size_t)(ci0 + row) * 1024 + gt] : 0.0f;
        }
        __syncthreads();

#pragma unroll
        for (int ci = 0; ci < 8; ci++) {
#pragma unroll
            for (int k = 0; k < 5; k++) {
                float a[8], bb[8];
#pragma unroll
                for (int j = 0; j < 8; j++) a[j] = ws[ci * 5 + k][ty + 16 * j];
#pragma unroll
                for (int j = 0; j < 8; j++) bb[j] = xs[ci][2 * (tx + 16 * j) + k];
#pragma unroll
                for (int cj = 0; cj < 8; cj++)
#pragma unroll
                    for (int tj = 0; tj < 8; tj++)
                        acc[cj][tj] = fmaf(a[cj], bb[tj], acc[cj][tj]);
            }
        }
        __syncthreads();
    }

    // fused global-average-pool: relu, sum over tile t, reduce 16 tx lanes,
    // atomic-accumulate per-sample feature sums.
    float* fb = feat + (size_t)b * 256;
#pragma unroll
    for (int cj = 0; cj < 8; cj++) {
        int co = co0 + ty + 16 * cj;
        float bv = bias[co];
        float s = 0.0f;
#pragma unroll
        for (int tj = 0; tj < 8; tj++)
            s += fmaxf(acc[cj][tj] + bv, 0.0f);
#pragma unroll
        for (int off = 8; off > 0; off >>= 1)
            s += __shfl_xor_sync(0xffffffffu, s, off);
        if (tx == 0) atomicAdd(&fb[co], s);
    }
}

// ---------------------------------------------------------------------------
__global__ void zero_feat_kernel()
{
    int i = blockIdx.x * 256 + threadIdx.x;
    if (i < 2 * 512 * 256) ((float*)g_feat)[i] = 0.0f;
}

// ---------------------------------------------------------------------------
// heads + softmax + hierarchical routing. 1 warp per sample.
// ---------------------------------------------------------------------------
__global__ __launch_bounds__(32)
void head_kernel(const float* __restrict__ wh1, const float* __restrict__ bh1,
                 const float* __restrict__ wh2, const float* __restrict__ bh2,
                 float* __restrict__ out)
{
    const int b = blockIdx.x;
    const int lane = threadIdx.x;
    const float* f1 = &g_feat[0][b][0];
    const float* f2 = &g_feat[1][b][0];
    const float inv_pool = 1.0f / 512.0f;

    float lg1[3], lg2[2];
#pragma unroll
    for (int cls = 0; cls < 3; cls++) {
        float s = 0.0f;
        for (int c = lane; c < 256; c += 32) s += f1[c] * wh1[cls * 256 + c];
#pragma unroll
        for (int off = 16; off > 0; off >>= 1) s += __shfl_xor_sync(0xffffffffu, s, off);
        lg1[cls] = s * inv_pool + bh1[cls];
    }
#pragma unroll
    for (int cls = 0; cls < 2; cls++) {
        float s = 0.0f;
        for (int c = lane; c < 256; c += 32) s += f2[c] * wh2[cls * 256 + c];
#pragma unroll
        for (int off = 16; off > 0; off >>= 1) s += __shfl_xor_sync(0xffffffffu, s, off);
        lg2[cls] = s * inv_pool + bh2[cls];
    }

    if (lane == 0) {
        float m = fmaxf(lg1[0], fmaxf(lg1[1], lg1[2]));
        float e0 = expf(lg1[0] - m), e1 = expf(lg1[1] - m), e2 = expf(lg1[2] - m);
        float inv = 1.0f / (e0 + e1 + e2);
        float p0 = e0 * inv, p1 = e1 * inv, p2 = e2 * inv;
        int pred = 0; float best = p0;
        if (p1 > best) { best = p1; pred = 1; }
        if (p2 > best) { best = p2; pred = 2; }

        float m2 = fmaxf(lg2[0], lg2[1]);
        float q0 = expf(lg2[0] - m2), q1 = expf(lg2[1] - m2);
        float inv2 = 1.0f / (q0 + q1);
        q0 *= inv2; q1 *= inv2;

        out[b * 4 + 0] = (pred == 0) ? p0 : 0.0f;
        out[b * 4 + 1] = (pred == 1) ? p1 : 0.0f;
        out[b * 4 + 2] = (pred == 2) ? q0 : 0.0f;
        out[b * 4 + 3] = (pred == 2) ? q1 : 0.0f;
    }
}

// ---------------------------------------------------------------------------
extern "C" void kernel_launch(void* const* d_in, const int* in_sizes, int n_in,
                              void* d_out, int out_size)
{
    (void)in_sizes; (void)n_in; (void)out_size;
    const float* x = (const float*)d_in[0];

    // per-net weight pointer sets: [w0,b0,w1,b1,w2,b2,wh,bh]
    const float* W[2][8];
    for (int net = 0; net < 2; net++)
        for (int i = 0; i < 8; i++)
            W[net][i] = (const float*)d_in[1 + net * 8 + i];

    float* out = (float*)d_out;

    float *a1, *feat;
    cudaGetSymbolAddress((void**)&a1, g_a1);
    cudaGetSymbolAddress((void**)&feat, g_feat);

    zero_feat_kernel<<<1024, 256>>>();

    for (int net = 0; net < 2; net++) {
        conv01_kernel<<<dim3(512, 8), 256>>>(x, W[net][0], W[net][1],
                                             W[net][2], W[net][3], a1);
        conv2_kernel<<<dim3(512, 4, 2), 256>>>(a1, W[net][4], W[net][5],
                                               feat + (size_t)net * 512 * 256);
    }

    head_kernel<<<512, 32>>>(W[0][6], W[0][7], W[1][6], W[1][7], out);
}

// round 3
// speedup vs baseline: 1.2631x; 1.2631x over previous
#include <cuda_runtime.h>
#include <math.h>

// ---------------------------------------------------------------------------
// HierarchicalCNN: two 3-layer strided conv1d nets + pooled heads + routing.
//
//   x    : [512, 2, 4096]
//   a1   : [512, 128, 1024]  (conv1 out, scratch, reused per net)
//   feat : [2][512][256]     (pooled sums; /512 in head)
//   out  : [512, 4]
//
// conv0 (2->64) fused into conv1. Mainloops use packed fma.rn.f32x2
// (Blackwell FFMA2): accumulators paired along c_out, 2 MACs per issue.
//
// SAME padding, stride 2, K=5: pad_lo = 1 -> input index = 2*t + k - 1.
// ---------------------------------------------------------------------------

__device__ float g_a1[(size_t)512 * 128 * 1024];
__device__ float g_feat[2][512][256];

// packed fp32x2 helpers --------------------------------------------------
__device__ __forceinline__ void fma2(unsigned long long& d,
                                     unsigned long long a,
                                     unsigned long long b) {
    asm("fma.rn.f32x2 %0, %1, %2, %0;" : "+l"(d) : "l"(a), "l"(b));
}
__device__ __forceinline__ unsigned long long pack2(float lo, float hi) {
    unsigned long long r;
    asm("mov.b64 %0, {%1, %2};" : "=l"(r) : "f"(lo), "f"(hi));
    return r;
}
__device__ __forceinline__ void unpack2(unsigned long long v, float& lo, float& hi) {
    asm("mov.b64 {%0, %1}, %2;" : "=f"(lo), "=f"(hi) : "l"(v));
}

#define WPITCH 132  // even pitch, 528B rows -> 16B-aligned float4 a-frag loads

// ---------------------------------------------------------------------------
// conv01: x[B,2,4096] -> (conv0+relu recomputed per tile) -> conv1+relu
//         -> a1[B,128,1024]
// CTA: (sample b, 128-wide t tile), all 128 c_out. 256 thr, 8x8 per thread.
// Thread maps: t = tx + 16*tj (tx=tid&15), co = ty*8 + cj (ty=tid>>4).
// ---------------------------------------------------------------------------
__global__ __launch_bounds__(256, 2)
void conv01_kernel(const float* __restrict__ x,
                   const float* __restrict__ w0,  // [64,2,5]
                   const float* __restrict__ b0,  // [64]
                   const float* __restrict__ w1,  // [128,64,5]
                   const float* __restrict__ b1,  // [128]
                   float* __restrict__ out)       // [512,128,1024]
{
    const int b   = blockIdx.x;
    const int tt0 = blockIdx.y * 128;
    const int tid = threadIdx.x;
    const int tx  = tid & 15;
    const int ty  = tid >> 4;

    const int tmid0 = 2 * tt0 - 1;       // layer-0 t window start (260 wide)
    const int x0    = 2 * tmid0 - 1;     // x window start (523 wide)

    __shared__ float xs0[2][524];
    __shared__ float w0s[64 * 10];
    __shared__ float b0s[64];
    __shared__ float ws[40][WPITCH];     // conv1 W tile [ci*5+k][co]
    __shared__ float xs[8][260];         // layer-0 activations [ci][t-halo]

    for (int i = tid; i < 640; i += 256) w0s[i] = w0[i];
    if (tid < 64) b0s[tid] = b0[tid];

    const float* xb = x + (size_t)b * 2 * 4096;
    for (int i = tid; i < 2 * 524; i += 256) {
        int row = i / 524, col = i % 524;
        int gx = x0 + col;
        xs0[row][col] = (gx >= 0 && gx < 4096) ? xb[(size_t)row * 4096 + gx] : 0.0f;
    }

    unsigned long long acc2[4][8];
#pragma unroll
    for (int i = 0; i < 4; i++)
#pragma unroll
        for (int j = 0; j < 8; j++) acc2[i][j] = 0ull;

    __syncthreads();

    for (int ci0 = 0; ci0 < 64; ci0 += 8) {
        // conv1 W tile: 40 x 128, 20 elems/thread
#pragma unroll
        for (int r = 0; r < 20; r++) {
            int flat = r * 256 + tid;
            int co = flat / 40;
            int kk = flat % 40;
            ws[kk][co] = w1[(size_t)co * (64 * 5) + ci0 * 5 + kk];
        }
        // layer-0 activations for this ci tile (recompute from x): 8 x 260
        for (int i = tid; i < 8 * 260; i += 256) {
            int row = i / 260, col = i % 260;
            int ci = ci0 + row;
            int tmid = tmid0 + col;
            float v = 0.0f;
            if (tmid >= 0 && tmid < 2048) {
                float a = b0s[ci];
                const float* wc = &w0s[ci * 10];
#pragma unroll
                for (int k = 0; k < 5; k++) a = fmaf(wc[k],     xs0[0][2 * col + k], a);
#pragma unroll
                for (int k = 0; k < 5; k++) a = fmaf(wc[5 + k], xs0[1][2 * col + k], a);
                v = fmaxf(a, 0.0f);
            }
            xs[row][col] = v;
        }
        __syncthreads();

#pragma unroll
        for (int ci = 0; ci < 8; ci++) {
#pragma unroll
            for (int k = 0; k < 5; k++) {
                const float4* wr =
                    reinterpret_cast<const float4*>(&ws[ci * 5 + k][ty * 8]);
                float4 al = wr[0], ah = wr[1];
                unsigned long long a2[4];
                a2[0] = pack2(al.x, al.y);
                a2[1] = pack2(al.z, al.w);
                a2[2] = pack2(ah.x, ah.y);
                a2[3] = pack2(ah.z, ah.w);
                unsigned long long b2[8];
#pragma unroll
                for (int j = 0; j < 8; j++) {
                    float bv = xs[ci][2 * (tx + 16 * j) + k];
                    b2[j] = pack2(bv, bv);
                }
#pragma unroll
                for (int cp = 0; cp < 4; cp++)
#pragma unroll
                    for (int tj = 0; tj < 8; tj++)
                        fma2(acc2[cp][tj], a2[cp], b2[tj]);
            }
        }
        __syncthreads();
    }

#pragma unroll
    for (int cp = 0; cp < 4; cp++) {
        int co_lo = ty * 8 + 2 * cp;
        float bl = b1[co_lo], bh = b1[co_lo + 1];
        float* ol = out + ((size_t)b * 128 + co_lo) * 1024 + tt0;
        float* oh = ol + 1024;
#pragma unroll
        for (int tj = 0; tj < 8; tj++) {
            float lo, hi;
            unpack2(acc2[cp][tj], lo, hi);
            int t = tx + 16 * tj;
            ol[t] = fmaxf(lo + bl, 0.0f);
            oh[t] = fmaxf(hi + bh, 0.0f);
        }
    }
}

// ---------------------------------------------------------------------------
// conv2: a1[B,128,1024] -> conv+relu -> fused mean-pool into feat sums.
// Same tile/threading scheme as conv01.
// ---------------------------------------------------------------------------
__global__ __launch_bounds__(256, 2)
void conv2_kernel(const float* __restrict__ in,    // [B,128,1024]
                  const float* __restrict__ w,     // [256,128,5]
                  const float* __restrict__ bias,  // [256]
                  float* __restrict__ feat)        // [B,256] sums
{
    const int b   = blockIdx.x;
    const int tt0 = blockIdx.y * 128;
    const int co0 = blockIdx.z * 128;
    const int tid = threadIdx.x;
    const int tx  = tid & 15;
    const int ty  = tid >> 4;

    __shared__ float ws[40][WPITCH];
    __shared__ float xs[8][260];

    unsigned long long acc2[4][8];
#pragma unroll
    for (int i = 0; i < 4; i++)
#pragma unroll
        for (int j = 0; j < 8; j++) acc2[i][j] = 0ull;

    const float* inb = in + (size_t)b * 128 * 1024;

    for (int ci0 = 0; ci0 < 128; ci0 += 8) {
#pragma unroll
        for (int r = 0; r < 20; r++) {
            int flat = r * 256 + tid;
            int co = flat / 40;
            int kk = flat % 40;
            ws[kk][co] = w[(size_t)(co0 + co) * (128 * 5) + ci0 * 5 + kk];
        }
        for (int i = tid; i < 8 * 260; i += 256) {
            int row = i / 260, col = i % 260;
            int gt = 2 * tt0 - 1 + col;
            xs[row][col] = (gt >= 0 && gt < 1024)
                               ? inb[(size_t)(ci0 + row) * 1024 + gt] : 0.0f;
        }
        __syncthreads();

#pragma unroll
        for (int ci = 0; ci < 8; ci++) {
#pragma unroll
            for (int k = 0; k < 5; k++) {
                const float4* wr =
                    reinterpret_cast<const float4*>(&ws[ci * 5 + k][ty * 8]);
                float4 al = wr[0], ah = wr[1];
                unsigned long long a2[4];
                a2[0] = pack2(al.x, al.y);
                a2[1] = pack2(al.z, al.w);
                a2[2] = pack2(ah.x, ah.y);
                a2[3] = pack2(ah.z, ah.w);
                unsigned long long b2[8];
#pragma unroll
                for (int j = 0; j < 8; j++) {
                    float bv = xs[ci][2 * (tx + 16 * j) + k];
                    b2[j] = pack2(bv, bv);
                }
#pragma unroll
                for (int cp = 0; cp < 4; cp++)
#pragma unroll
                    for (int tj = 0; tj < 8; tj++)
                        fma2(acc2[cp][tj], a2[cp], b2[tj]);
            }
        }
        __syncthreads();
    }

    // fused mean-pool: relu, sum over tile t, reduce 16 tx lanes, atomicAdd.
    float* fb = feat + (size_t)b * 256;
#pragma unroll
    for (int cp = 0; cp < 4; cp++) {
        int co_lo = co0 + ty * 8 + 2 * cp;
        float bl = bias[co_lo], bh = bias[co_lo + 1];
        float sl = 0.0f, sh = 0.0f;
#pragma unroll
        for (int tj = 0; tj < 8; tj++) {
            float lo, hi;
            unpack2(acc2[cp][tj], lo, hi);
            sl += fmaxf(lo + bl, 0.0f);
            sh += fmaxf(hi + bh, 0.0f);
        }
#pragma unroll
        for (int off = 8; off > 0; off >>= 1) {
            sl += __shfl_xor_sync(0xffffffffu, sl, off);
            sh += __shfl_xor_sync(0xffffffffu, sh, off);
        }
        if (tx == 0) {
            atomicAdd(&fb[co_lo], sl);
            atomicAdd(&fb[co_lo + 1], sh);
        }
    }
}

// ---------------------------------------------------------------------------
__global__ void zero_feat_kernel()
{
    int i = blockIdx.x * 256 + threadIdx.x;
    if (i < 2 * 512 * 256) ((float*)g_feat)[i] = 0.0f;
}

// ---------------------------------------------------------------------------
// heads + softmax + hierarchical routing. 1 warp per sample.
// ---------------------------------------------------------------------------
__global__ __launch_bounds__(32)
void head_kernel(const float* __restrict__ wh1, const float* __restrict__ bh1,
                 const float* __restrict__ wh2, const float* __restrict__ bh2,
                 float* __restrict__ out)
{
    const int b = blockIdx.x;
    const int lane = threadIdx.x;
    const float* f1 = &g_feat[0][b][0];
    const float* f2 = &g_feat[1][b][0];
    const float inv_pool = 1.0f / 512.0f;

    float lg1[3], lg2[2];
#pragma unroll
    for (int cls = 0; cls < 3; cls++) {
        float s = 0.0f;
        for (int c = lane; c < 256; c += 32) s += f1[c] * wh1[cls * 256 + c];
#pragma unroll
        for (int off = 16; off > 0; off >>= 1) s += __shfl_xor_sync(0xffffffffu, s, off);
        lg1[cls] = s * inv_pool + bh1[cls];
    }
#pragma unroll
    for (int cls = 0; cls < 2; cls++) {
        float s = 0.0f;
        for (int c = lane; c < 256; c += 32) s += f2[c] * wh2[cls * 256 + c];
#pragma unroll
        for (int off = 16; off > 0; off >>= 1) s += __shfl_xor_sync(0xffffffffu, s, off);
        lg2[cls] = s * inv_pool + bh2[cls];
    }

    if (lane == 0) {
        float m = fmaxf(lg1[0], fmaxf(lg1[1], lg1[2]));
        float e0 = expf(lg1[0] - m), e1 = expf(lg1[1] - m), e2 = expf(lg1[2] - m);
        float inv = 1.0f / (e0 + e1 + e2);
        float p0 = e0 * inv, p1 = e1 * inv, p2 = e2 * inv;
        int pred = 0; float best = p0;
        if (p1 > best) { best = p1; pred = 1; }
        if (p2 > best) { best = p2; pred = 2; }

        float m2 = fmaxf(lg2[0], lg2[1]);
        float q0 = expf(lg2[0] - m2), q1 = expf(lg2[1] - m2);
        float inv2 = 1.0f / (q0 + q1);
        q0 *= inv2; q1 *= inv2;

        out[b * 4 + 0] = (pred == 0) ? p0 : 0.0f;
        out[b * 4 + 1] = (pred == 1) ? p1 : 0.0f;
        out[b * 4 + 2] = (pred == 2) ? q0 : 0.0f;
        out[b * 4 + 3] = (pred == 2) ? q1 : 0.0f;
    }
}

// ---------------------------------------------------------------------------
extern "C" void kernel_launch(void* const* d_in, const int* in_sizes, int n_in,
                              void* d_out, int out_size)
{
    (void)in_sizes; (void)n_in; (void)out_size;
    const float* x = (const float*)d_in[0];

    const float* W[2][8];
    for (int net = 0; net < 2; net++)
        for (int i = 0; i < 8; i++)
            W[net][i] = (const float*)d_in[1 + net * 8 + i];

    float* out = (float*)d_out;

    float *a1, *feat;
    cudaGetSymbolAddress((void**)&a1, g_a1);
    cudaGetSymbolAddress((void**)&feat, g_feat);

    zero_feat_kernel<<<1024, 256>>>();

    for (int net = 0; net < 2; net++) {
        conv01_kernel<<<dim3(512, 8), 256>>>(x, W[net][0], W[net][1],
                                             W[net][2], W[net][3], a1);
        conv2_kernel<<<dim3(512, 4, 2), 256>>>(a1, W[net][4], W[net][5],
                                               feat + (size_t)net * 512 * 256);
    }

    head_kernel<<<512, 32>>>(W[0][6], W[0][7], W[1][6], W[1][7], out);
}